// round 3
// baseline (speedup 1.0000x reference)
#include <cuda_runtime.h>
#include <math.h>

// Problem dims
#define BB 8
#define LL_ 512
#define DD 768
#define HH 12
#define DKK 64
#define MTOT 96      // BB*HH
#define NN 512

// Output layout (flattened tuple concat)
#define OFF_CTX 0
#define OFF_D   37748736
#define OFF_D0  62914560
#define OFF_LOSS 62963712

// ---------------- scratch (device globals; no allocations allowed) ----------------
__device__ float g_q[BB * LL_ * DD];
__device__ float g_k[BB * LL_ * DD];
__device__ float g_R[BB * LL_];
__device__ float g_m[BB * LL_];
__device__ float g_A[MTOT * NN * NN];     // exp(scores)
__device__ float g_LLm[MTOT * NN * NN];   // Laplacian -> becomes inverse in place
__device__ float g_Fcol[MTOT * NN * 64];  // saved column block for GJ step
__device__ float g_colsum[MTOT * NN];
__device__ float g_diag[MTOT * NN];
__device__ float g_bce[BB * LL_];

// ---------------- projection GEMM: C = (X @ W + bias) * scale ----------------
// X [4096,768], W [768,768]; 64x64 tile, K-chunk 16, 256 thr, 4x4 micro.
__global__ __launch_bounds__(256) void k_proj(const float* __restrict__ X,
                                              const float* __restrict__ W,
                                              const float* __restrict__ bias,
                                              float scale, int which)
{
    __shared__ __align__(16) float As[64 * 17];
    __shared__ __align__(16) float Bs[16 * 64];
    float* C = which ? g_k : g_q;
    int tx = threadIdx.x & 15, ty = threadIdx.x >> 4;
    int r0 = blockIdx.y * 64, c0 = blockIdx.x * 64;
    float acc[4][4] = {};
    for (int k0 = 0; k0 < 768; k0 += 16) {
        int idx = threadIdx.x * 4;
        int ar = idx >> 4, ac = idx & 15;
        float4 av = *(const float4*)&X[(r0 + ar) * 768 + k0 + ac];
        As[ar * 17 + ac + 0] = av.x; As[ar * 17 + ac + 1] = av.y;
        As[ar * 17 + ac + 2] = av.z; As[ar * 17 + ac + 3] = av.w;
        int br_ = idx >> 6, bc = idx & 63;
        *(float4*)&Bs[br_ * 64 + bc] = *(const float4*)&W[(k0 + br_) * 768 + c0 + bc];
        __syncthreads();
#pragma unroll
        for (int kk = 0; kk < 16; kk++) {
            float4 bv = *(float4*)&Bs[kk * 64 + tx * 4];
#pragma unroll
            for (int i = 0; i < 4; i++) {
                float a = As[(ty * 4 + i) * 17 + kk];
                acc[i][0] += a * bv.x; acc[i][1] += a * bv.y;
                acc[i][2] += a * bv.z; acc[i][3] += a * bv.w;
            }
        }
        __syncthreads();
    }
#pragma unroll
    for (int i = 0; i < 4; i++)
#pragma unroll
        for (int j = 0; j < 4; j++) {
            int r = r0 + ty * 4 + i, c = c0 + tx * 4 + j;
            C[r * 768 + c] = (acc[i][j] + bias[c]) * scale;
        }
}

// ---------------- root scores + mask precompute ----------------
__global__ __launch_bounds__(256) void k_root(const float* __restrict__ X,
                                              const float* __restrict__ Wr,
                                              const float* __restrict__ br,
                                              const float* __restrict__ mask)
{
    int warp = (blockIdx.x * blockDim.x + threadIdx.x) >> 5;
    int lane = threadIdx.x & 31;
    if (warp >= BB * LL_) return;
    float s = 0.f;
    for (int t = lane; t < 768; t += 32) s += X[warp * 768 + t] * Wr[t];
#pragma unroll
    for (int o = 16; o > 0; o >>= 1) s += __shfl_down_sync(0xffffffff, s, o);
    if (lane == 0) {
        float m = mask[warp] * (-1.0f / 10000.0f);
        float root = fmaxf(s + br[0] - m * 50.0f, -40.0f);
        g_R[warp] = expf(root);
        g_m[warp] = m;
    }
}

// ---------------- scores -> A = exp(clip(q.k - masks, -40)) ----------------
__global__ __launch_bounds__(256) void k_scores()
{
    int m = blockIdx.z, b = m / HH, h = m % HH;
    int i0 = blockIdx.y * 64, j0 = blockIdx.x * 64;
    __shared__ float Qs[64 * 65];
    __shared__ float Ks[64 * 65];
    const float* qb = g_q + (size_t)b * LL_ * DD;
    const float* kb = g_k + (size_t)b * LL_ * DD;
    for (int t = threadIdx.x; t < 4096; t += 256) {
        int r = t >> 6, c = t & 63;
        Qs[r * 65 + c] = qb[(i0 + r) * DD + h * 64 + c];
        Ks[r * 65 + c] = kb[(j0 + r) * DD + h * 64 + c];
    }
    __syncthreads();
    int tx = threadIdx.x & 15, ty = threadIdx.x >> 4;
    float acc[4][4] = {};
#pragma unroll
    for (int kk = 0; kk < 64; kk++) {
        float bq[4];
#pragma unroll
        for (int j = 0; j < 4; j++) bq[j] = Ks[(tx * 4 + j) * 65 + kk];
#pragma unroll
        for (int i = 0; i < 4; i++) {
            float a = Qs[(ty * 4 + i) * 65 + kk];
#pragma unroll
            for (int j = 0; j < 4; j++) acc[i][j] += a * bq[j];
        }
    }
    float* Am = g_A + (size_t)m * NN * NN;
#pragma unroll
    for (int i = 0; i < 4; i++) {
        int gi = i0 + ty * 4 + i;
        float mi = g_m[b * LL_ + gi];
#pragma unroll
        for (int j = 0; j < 4; j++) {
            int gj = j0 + tx * 4 + j;
            float s = acc[i][j] - 50.0f * (mi + g_m[b * LL_ + gj]);
            s = fmaxf(s, -40.0f);
            Am[gi * NN + gj] = expf(s);
        }
    }
}

// ---------------- column sums of A ----------------
__global__ void k_colsum()
{
    int m = blockIdx.y;
    int j = blockIdx.x * 128 + threadIdx.x;
    const float* Am = g_A + (size_t)m * NN * NN;
    float s = 0.f;
    for (int i = 0; i < NN; i++) s += Am[i * NN + j];
    g_colsum[m * NN + j] = s;
}

// ---------------- build Laplacian LL = diag(colsum + R) - A ----------------
__global__ void k_buildLL()
{
    int idx = blockIdx.x * 256 + threadIdx.x;
    int m = idx / (NN * NN);
    int rem = idx - m * NN * NN;
    int i = rem / NN, j = rem - i * NN;
    float v = -g_A[idx];
    if (i == j) {
        int b = m / HH;
        v += g_colsum[m * NN + j] + g_R[b * LL_ + j];
    }
    g_LLm[idx] = v;
}

// ---------------- blocked Gauss-Jordan inversion, NB=64, 8 steps ----------------
// step kernel 1: save column block to scratch, invert pivot block in smem
__global__ __launch_bounds__(256) void k_pivot(int kb)
{
    int m = blockIdx.x;
    float* A = g_LLm + (size_t)m * NN * NN;
    float* F = g_Fcol + (size_t)m * NN * 64;
    for (int t = threadIdx.x; t < NN * 64; t += 256) {
        int r = t >> 6, c = t & 63;
        F[t] = A[r * NN + kb * 64 + c];
    }
    __shared__ float P[64 * 65];
    __shared__ float s_col[64];
    __shared__ float s_piv;
    for (int t = threadIdx.x; t < 4096; t += 256) {
        int r = t >> 6, c = t & 63;
        P[r * 65 + c] = A[(kb * 64 + r) * NN + kb * 64 + c];
    }
    __syncthreads();
    for (int k = 0; k < 64; k++) {
        if (threadIdx.x == 0) s_piv = 1.0f / P[k * 65 + k];
        __syncthreads();
        if (threadIdx.x < 64) s_col[threadIdx.x] = P[threadIdx.x * 65 + k];
        __syncthreads();
        if (threadIdx.x < 64) {
            int j = threadIdx.x;
            P[k * 65 + j] = (j == k) ? s_piv : P[k * 65 + j] * s_piv;
        }
        __syncthreads();
        for (int t = threadIdx.x; t < 4096; t += 256) {
            int i = t >> 6, j = t & 63;
            if (i != k) {
                P[i * 65 + j] = (j == k) ? (-s_col[i] * s_piv)
                                         : P[i * 65 + j] - s_col[i] * P[k * 65 + j];
            }
        }
        __syncthreads();
    }
    for (int t = threadIdx.x; t < 4096; t += 256) {
        int r = t >> 6, c = t & 63;
        A[(kb * 64 + r) * NN + kb * 64 + c] = P[r * 65 + c];
    }
}

// step kernel 2: row-block scale  A[K][J] = Pinv @ A[K][J]  (J != K)
__global__ __launch_bounds__(256) void k_rowscale(int kb)
{
    int jt = blockIdx.x; if (jt >= kb) jt++;
    int m = blockIdx.y;
    float* A = g_LLm + (size_t)m * NN * NN;
    __shared__ float Ps[64 * 65];
    __shared__ __align__(16) float Ts[64 * 64];
    for (int t = threadIdx.x; t < 4096; t += 256) {
        int r = t >> 6, c = t & 63;
        Ps[r * 65 + c] = A[(kb * 64 + r) * NN + kb * 64 + c];
        Ts[r * 64 + c] = A[(kb * 64 + r) * NN + jt * 64 + c];
    }
    __syncthreads();
    int tx = threadIdx.x & 15, ty = threadIdx.x >> 4;
    float acc[4][4] = {};
#pragma unroll
    for (int kk = 0; kk < 64; kk++) {
        float4 bv = *(float4*)&Ts[kk * 64 + tx * 4];
#pragma unroll
        for (int i = 0; i < 4; i++) {
            float a = Ps[(ty * 4 + i) * 65 + kk];
            acc[i][0] += a * bv.x; acc[i][1] += a * bv.y;
            acc[i][2] += a * bv.z; acc[i][3] += a * bv.w;
        }
    }
#pragma unroll
    for (int i = 0; i < 4; i++)
#pragma unroll
        for (int j = 0; j < 4; j++)
            A[(kb * 64 + ty * 4 + i) * NN + jt * 64 + tx * 4 + j] = acc[i][j];
}

// step kernel 3: trailing update  A[I][J] -= F @ A[K][J];  A[I][K] = -F @ Pinv
__global__ __launch_bounds__(256) void k_update(int kb)
{
    int jt = blockIdx.x;                 // 0..7 incl. kb
    int it = blockIdx.y; if (it >= kb) it++;  // skip kb
    int m = blockIdx.z;
    float* A = g_LLm + (size_t)m * NN * NN;
    const float* F = g_Fcol + (size_t)m * NN * 64;
    __shared__ float Fs[64 * 65];
    __shared__ __align__(16) float Bs[64 * 64];
    for (int t = threadIdx.x; t < 4096; t += 256) {
        int r = t >> 6, c = t & 63;
        Fs[r * 65 + c] = F[(it * 64 + r) * 64 + c];
        Bs[r * 64 + c] = A[(kb * 64 + r) * NN + jt * 64 + c];
    }
    __syncthreads();
    int tx = threadIdx.x & 15, ty = threadIdx.x >> 4;
    float acc[4][4] = {};
#pragma unroll
    for (int kk = 0; kk < 64; kk++) {
        float4 bv = *(float4*)&Bs[kk * 64 + tx * 4];
#pragma unroll
        for (int i = 0; i < 4; i++) {
            float a = Fs[(ty * 4 + i) * 65 + kk];
            acc[i][0] += a * bv.x; acc[i][1] += a * bv.y;
            acc[i][2] += a * bv.z; acc[i][3] += a * bv.w;
        }
    }
#pragma unroll
    for (int i = 0; i < 4; i++)
#pragma unroll
        for (int j = 0; j < 4; j++) {
            int gi = it * 64 + ty * 4 + i, gj = jt * 64 + tx * 4 + j;
            float base = (jt == kb) ? 0.0f : A[gi * NN + gj];
            A[gi * NN + gj] = base - acc[i][j];
        }
}

// ---------------- diag + d0 ----------------
__global__ void k_diag(float* __restrict__ out)
{
    int idx = blockIdx.x * 256 + threadIdx.x;  // 96*512
    int m = idx / NN, i = idx - m * NN;
    float dv = g_LLm[(size_t)m * NN * NN + i * NN + i];
    g_diag[idx] = dv;
    int b = m / HH;
    out[OFF_D0 + idx] = g_R[b * LL_ + i] * dv;
}

// ---------------- d = A * (diag[j] - LLinv[j][i]) ----------------
__global__ void k_dmat(float* __restrict__ out)
{
    int m = blockIdx.z;
    int i0 = blockIdx.y * 32, j0 = blockIdx.x * 32;
    __shared__ float Ts[32 * 33];
    const float* Lm = g_LLm + (size_t)m * NN * NN;
    for (int t = threadIdx.x; t < 1024; t += 256) {
        int r = t >> 5, c = t & 31;
        Ts[r * 33 + c] = Lm[(j0 + r) * NN + i0 + c];   // rows=j, cols=i (coalesced)
    }
    __syncthreads();
    const float* Am = g_A + (size_t)m * NN * NN;
    float* Dm = out + OFF_D + (size_t)m * NN * NN;
    for (int t = threadIdx.x; t < 1024; t += 256) {
        int li = t >> 5, lj = t & 31;
        int gi = i0 + li, gj = j0 + lj;
        float a = Am[gi * NN + gj];
        Dm[gi * NN + gj] = a * (g_diag[m * NN + gj] - Ts[lj * 33 + li]);
    }
}

// ---------------- context = (masked d)^T @ x ----------------
__global__ __launch_bounds__(256) void k_context(const float* __restrict__ out_d,
                                                 const float* __restrict__ X,
                                                 float* __restrict__ out)
{
    int m = blockIdx.z, b = m / HH;
    int q0 = blockIdx.y * 64, n0 = blockIdx.x * 64;
    __shared__ float Ds[32 * 64];
    __shared__ __align__(16) float Bs[32 * 64];
    const float* dm = out_d + OFF_D + (size_t)m * NN * NN;
    const float* xb = X + (size_t)b * LL_ * DD;
    const float* mm = g_m + b * LL_;
    int tx = threadIdx.x & 15, ty = threadIdx.x >> 4;
    float acc[4][4] = {};
    for (int k0 = 0; k0 < NN; k0 += 32) {
        for (int t = threadIdx.x; t < 2048; t += 256) {
            int kk = t >> 6, c = t & 63;
            float v = dm[(k0 + kk) * NN + q0 + c];
            float z = mm[k0 + kk] + mm[q0 + c];
            Ds[kk * 64 + c] = (z != 0.0f) ? 0.0f : v;
            Bs[kk * 64 + c] = xb[(k0 + kk) * DD + n0 + c];
        }
        __syncthreads();
#pragma unroll
        for (int kk = 0; kk < 32; kk++) {
            float4 bv = *(float4*)&Bs[kk * 64 + tx * 4];
#pragma unroll
            for (int i = 0; i < 4; i++) {
                float a = Ds[kk * 64 + ty * 4 + i];
                acc[i][0] += a * bv.x; acc[i][1] += a * bv.y;
                acc[i][2] += a * bv.z; acc[i][3] += a * bv.w;
            }
        }
        __syncthreads();
    }
    float* Cm = out + OFF_CTX + (size_t)m * LL_ * DD;
#pragma unroll
    for (int i = 0; i < 4; i++)
#pragma unroll
        for (int j = 0; j < 4; j++)
            Cm[(q0 + ty * 4 + i) * DD + n0 + tx * 4 + j] = acc[i][j];
}

// ---------------- BCE loss ----------------
__global__ void k_bce(const float* __restrict__ out, const int* __restrict__ labels)
{
    int idx = blockIdx.x * 256 + threadIdx.x;  // 4096
    if (idx >= BB * LL_) return;
    int b = idx / LL_, i = idx - b * LL_;
    float y = (float)labels[idx];
    float s = 0.f;
    for (int h = 0; h < HH; h++) {
        float p = out[OFF_D0 + (b * HH + h) * LL_ + i];
        p = fminf(fmaxf(p, 1e-5f), 1.0f - 1e-5f);
        s += -(y * logf(p) + (1.0f - y) * logf(1.0f - p));
    }
    g_bce[idx] = y * s;
}

__global__ void k_loss(float* __restrict__ out)
{
    __shared__ float red[256];
    float s = 0.f;
    for (int t = threadIdx.x; t < BB * LL_; t += 256) s += g_bce[t];
    red[threadIdx.x] = s;
    __syncthreads();
    for (int o = 128; o > 0; o >>= 1) {
        if (threadIdx.x < o) red[threadIdx.x] += red[threadIdx.x + o];
        __syncthreads();
    }
    if (threadIdx.x == 0) out[OFF_LOSS] = red[0] / (float)(BB * LL_);
}

// ---------------- launch ----------------
extern "C" void kernel_launch(void* const* d_in, const int* in_sizes, int n_in,
                              void* d_out, int out_size)
{
    const float* x    = (const float*)d_in[0];
    const float* mask = (const float*)d_in[1];
    const int* roots_label = (const int*)d_in[2];
    // d_in[3] root_mask: only checked non-None in the reference, unused
    const float* Wq = (const float*)d_in[4];
    const float* bq = (const float*)d_in[5];
    const float* Wk = (const float*)d_in[6];
    const float* bk = (const float*)d_in[7];
    const float* Wr = (const float*)d_in[8];
    const float* br = (const float*)d_in[9];
    float* out = (float*)d_out;

    float qscale = 1.0f / sqrtf((float)DD);
    dim3 gproj(12, 64);
    k_proj<<<gproj, 256>>>(x, Wq, bq, qscale, 0);
    k_proj<<<gproj, 256>>>(x, Wk, bk, 1.0f, 1);
    k_root<<<512, 256>>>(x, Wr, br, mask);

    k_scores<<<dim3(8, 8, MTOT), 256>>>();
    k_colsum<<<dim3(4, MTOT), 128>>>();
    k_buildLL<<<(MTOT * NN * NN) / 256, 256>>>();

    for (int kb = 0; kb < 8; kb++) {
        k_pivot<<<MTOT, 256>>>(kb);
        k_rowscale<<<dim3(7, MTOT), 256>>>(kb);
        k_update<<<dim3(8, 7, MTOT), 256>>>(kb);
    }

    k_diag<<<(MTOT * NN) / 256, 256>>>(out);
    k_dmat<<<dim3(16, 16, MTOT), 256>>>(out);
    k_context<<<dim3(12, 8, MTOT), 256>>>(out, x, out);
    k_bce<<<16, 256>>>(out, roots_label);
    k_loss<<<1, 256>>>(out);
}